// round 12
// baseline (speedup 1.0000x reference)
#include <cuda_runtime.h>
#include <cuda_fp16.h>
#include <cstdint>

// LoRAConv1D: out = x @ W + b + 4.0 * (x @ A) @ B
//   x:[8192,1600]f32  W:[1600,4800]f32  b:[4800]  A:[1600,8]  B:[8,4800]
//
// Single-product fp16 tensor path (sm_103 non-'a' target):
//  1) prep kernel (one launch): x -> fp16, and W' = W + 4*A@B -> fp16
//     transposed [N,K] (N padded 4800->4864, pad rows stay zero)
//  2) out = fp16(x)*fp16(W') + b, fp32 accum via mma.sync m16n8k16
//     (calibrated rel err 2.9326e-4 < 1e-3)
//  GEMM: BM=128 BN=128 BK=64, 256 threads (8 warps, 2x4), warp tile 64x32,
//  3-stage cp.async (32KB/stage), 2 CTAs/SM. NEW vs R10/R11: A fragments
//  are software-pipelined through a 2-deep register buffer (each ldsm is
//  issued one mt-slot ahead, covered by 4 mmas), incl. across kk and the
//  iteration barrier. B-fragment pipelining unchanged.

#define M_TOT 8192
#define N_TOT 4800
#define N_PAD 4864
#define K_TOT 1600
#define RANK  8

#define BM 128
#define BN 128
#define BK 64
#define KITERS (K_TOT / BK)        // 25

// stage layout (bytes): A[128*128] B[128*128]
#define A_OFF 0
#define B_OFF 16384
#define STAGE_BYTES 32768
#define SMEM_TOTAL (3 * STAGE_BYTES)   // 98304 per CTA -> 2 CTAs/SM

// prep kernel block split
#define CONV_BLOCKS 6400               // 6400*256*8 = 13.1M = M*K
#define FUSE_NB (N_TOT / 32)           // 150
#define FUSE_KB (K_TOT / 64)           // 25
#define FUSE_BLOCKS (FUSE_NB * FUSE_KB)  // 3750

// ---------------- device scratch (static, alloc-free) ----------------------
__device__ __half g_x[(size_t)M_TOT * K_TOT];    // fp16 x
__device__ __half g_w[(size_t)N_PAD * K_TOT];    // [N_PAD,K] fp16 W' (pad=0)

// ---------------- helpers ---------------------------------------------------
__device__ __forceinline__ uint32_t smem_u32(const void* p) {
    uint32_t a;
    asm("{ .reg .u64 t; cvta.to.shared.u64 t, %1; cvt.u32.u64 %0, t; }"
        : "=r"(a) : "l"(p));
    return a;
}
// 128B-pitch SW128 swizzle: 16B chunk ch of row -> ch ^ (row & 7).
__device__ __forceinline__ uint32_t swz128(int row, int ch) {
    return (uint32_t)(row * 128 + 16 * (ch ^ (row & 7)));
}
__device__ __forceinline__ void cp16(uint32_t dst, const void* src) {
    asm volatile("cp.async.cg.shared.global [%0], [%1], 16;"
                 :: "r"(dst), "l"(src));
}
#define CP_COMMIT() asm volatile("cp.async.commit_group;")
#define CP_WAIT1()  asm volatile("cp.async.wait_group 1;")

__device__ __forceinline__ void ldm_x4(uint32_t* r, uint32_t addr) {
    asm volatile("ldmatrix.sync.aligned.m8n8.x4.shared.b16 {%0,%1,%2,%3}, [%4];"
                 : "=r"(r[0]), "=r"(r[1]), "=r"(r[2]), "=r"(r[3]) : "r"(addr));
}
__device__ __forceinline__ void mma_f16(float* d, const uint32_t* a,
                                        const uint32_t* b) {
    asm volatile(
        "mma.sync.aligned.m16n8k16.row.col.f32.f16.f16.f32 "
        "{%0,%1,%2,%3}, {%4,%5,%6,%7}, {%8,%9}, {%0,%1,%2,%3};"
        : "+f"(d[0]), "+f"(d[1]), "+f"(d[2]), "+f"(d[3])
        : "r"(a[0]), "r"(a[1]), "r"(a[2]), "r"(a[3]), "r"(b[0]), "r"(b[1]));
}

// ---------------- kernel 1: merged prep (x convert + W fuse/transpose) ------
__global__ void prep_kernel(const float* __restrict__ x,
                            const float* __restrict__ W,
                            const float* __restrict__ A,
                            const float* __restrict__ Bl) {
    const int tid = threadIdx.x;
    if (blockIdx.x < CONV_BLOCKS) {
        size_t base = ((size_t)blockIdx.x * 256 + tid) * 8;
        float v[8];
        *(float4*)(v)     = *(const float4*)(x + base);
        *(float4*)(v + 4) = *(const float4*)(x + base + 4);
        uint4 ph;
        __half* hp = (__half*)&ph;
#pragma unroll
        for (int j = 0; j < 8; j++) hp[j] = __float2half_rn(v[j]);
        *(uint4*)((char*)g_x + base * 2) = ph;
        return;
    }

    // ---- fuse part: 32n x 64k tile, coalesced 16B stores ----
    __shared__ uint32_t sh[32][37];
    const int bid = blockIdx.x - CONV_BLOCKS;
    const int nb = bid % FUSE_NB, kb = bid / FUSE_NB;
    const int n0 = nb * 32, k0 = kb * 64;
    const int tx = tid & 31, ty = tid >> 5;      // 32 x 8

#pragma unroll
    for (int w2 = 0; w2 < 4; w2++) {
        __half pair[2];
#pragma unroll
        for (int e = 0; e < 2; e++) {
            const int k = k0 + ty * 8 + w2 * 2 + e;
            const int n = n0 + tx;
            float acc = W[(size_t)k * N_TOT + n];
#pragma unroll
            for (int r = 0; r < RANK; r++)
                acc += 4.0f * A[k * RANK + r] * Bl[r * N_TOT + n];
            pair[e] = __float2half_rn(acc);
        }
        sh[tx][ty * 4 + w2] = *(const uint32_t*)pair;
    }
    __syncthreads();
    {
        const int n_local = tid >> 3;
        const int jw = (tid & 7) * 4;
        uint4 v;
        v.x = sh[n_local][jw + 0];
        v.y = sh[n_local][jw + 1];
        v.z = sh[n_local][jw + 2];
        v.w = sh[n_local][jw + 3];
        *(uint4*)(g_w + (size_t)(n0 + n_local) * K_TOT + k0 + (tid & 7) * 8) = v;
    }
}

// ---------------- kernel 2: fp16 mma.sync GEMM ------------------------------
// 8 warps: wm = wid&1 (64-row slab), wn = wid>>1 (32-col slab).
// Warp tile 64x32: mt=4 (m16), nt=4 (n8) -> acc[4][4][4] = 64 regs.
__global__ __launch_bounds__(256, 2)
void gemm_kernel(const float* __restrict__ bias, float* __restrict__ out) {
    extern __shared__ char smem[];
    const uint32_t sb = smem_u32(smem);
    const int tid = threadIdx.x, lane = tid & 31, wid = tid >> 5;
    const int wm = wid & 1;
    const int wn = wid >> 1;
    const int m0 = blockIdx.y * BM;
    const int n0 = blockIdx.x * BN;
    const uint32_t l7 = lane & 7;

    uint32_t aBase[4];
#pragma unroll
    for (int mt = 0; mt < 4; mt++)
        aBase[mt] = A_OFF + (uint32_t)(wm * 64 + mt * 16 + (lane & 15)) * 128;
    uint32_t bBase[2];
#pragma unroll
    for (int p = 0; p < 2; p++)
        bBase[p] = B_OFF +
            (uint32_t)(wn * 32 + (2 * p + ((lane >> 4) & 1)) * 8 + l7) * 128;
    const uint32_t aSel = lane >> 4;
    const uint32_t bSel = (lane >> 3) & 1;

    float acc[4][4][4];
#pragma unroll
    for (int i = 0; i < 4; i++)
#pragma unroll
        for (int j = 0; j < 4; j++)
#pragma unroll
            for (int k = 0; k < 4; k++) acc[i][j][k] = 0.0f;

    auto load_stage = [&](int s, int k0) {
        const uint32_t st = sb + s * STAGE_BYTES;
#pragma unroll
        for (int i = 0; i < 4; i++) {
            int idx = tid + i * 256;
            int row = idx >> 3, ch = idx & 7;
            cp16(st + A_OFF + swz128(row, ch),
                 g_x + (size_t)(m0 + row) * K_TOT + k0 + ch * 8);
        }
#pragma unroll
        for (int i = 0; i < 4; i++) {
            int idx = tid + i * 256;
            int row = idx >> 3, ch = idx & 7;
            cp16(st + B_OFF + swz128(row, ch),
                 g_w + (size_t)(n0 + row) * K_TOT + k0 + ch * 8);
        }
    };

    auto xA = [&](int kk) { return 16u * (((uint32_t)(kk * 2) + aSel) ^ l7); };
    auto xB = [&](int kk) { return 16u * (((uint32_t)(kk * 2) + bSel) ^ l7); };

    load_stage(0, 0);       CP_COMMIT();
    load_stage(1, BK);      CP_COMMIT();
    CP_WAIT1();
    __syncthreads();

    // fragment pipelines: B double buffer (per kk), A 2-deep rolling buffer
    uint32_t bf[2][2][4];
    uint32_t areg[2][4];
    {
        const uint32_t st0 = sb + 0 * STAGE_BYTES;
#pragma unroll
        for (int p = 0; p < 2; p++) ldm_x4(bf[0][p], st0 + bBase[p] + xB(0));
        ldm_x4(areg[0], st0 + aBase[0] + xA(0));
    }

    int cur = 0, nxt = 2;
    for (int t = 0; t < KITERS; t++) {
        const uint32_t st = sb + cur * STAGE_BYTES;

        if (t + 2 < KITERS) load_stage(nxt, (t + 2) * BK);
        CP_COMMIT();

#pragma unroll
        for (int kk = 0; kk < 4; kk++) {
            const int cb = kk & 1;
            if (kk < 3) {                     // prefetch next kk's B frags
#pragma unroll
                for (int p = 0; p < 2; p++)
                    ldm_x4(bf[cb ^ 1][p], st + bBase[p] + xB(kk + 1));
            }
#pragma unroll
            for (int mt = 0; mt < 4; mt++) {
                const int pa = (4 * kk + mt) & 1;
                // prefetch next A fragment (covered by the 4 mmas below)
                if (mt < 3)
                    ldm_x4(areg[pa ^ 1], st + aBase[mt + 1] + xA(kk));
                else if (kk < 3)
                    ldm_x4(areg[pa ^ 1], st + aBase[0] + xA(kk + 1));
#pragma unroll
                for (int p = 0; p < 2; p++) {
                    mma_f16(acc[mt][2 * p],     areg[pa], &bf[cb][p][0]);
                    mma_f16(acc[mt][2 * p + 1], areg[pa], &bf[cb][p][2]);
                }
            }
        }

        CP_WAIT1();
        const int nxts = (cur == 2) ? 0 : cur + 1;
        if (t + 1 < KITERS) {
            // cross-iteration prefetch from stage t+1 (race-free: the next
            // iteration's cp.async writes target stage t+2, not t+1)
            const uint32_t stn = sb + nxts * STAGE_BYTES;
#pragma unroll
            for (int p = 0; p < 2; p++)
                ldm_x4(bf[0][p], stn + bBase[p] + xB(0));
            ldm_x4(areg[0], stn + aBase[0] + xA(0));   // next iter kk0 mt0 (pa=0)
        }
        __syncthreads();
        cur = nxts;
        nxt = (nxt == 2) ? 0 : nxt + 1;
    }

    // ---- epilogue: add bias, float2 stores (guard N edge: pad 4800..4863) --
    const int r0 = lane >> 2, c0 = (lane & 3) * 2;
#pragma unroll
    for (int mt = 0; mt < 4; mt++)
#pragma unroll
        for (int nt = 0; nt < 4; nt++) {
            const int col = n0 + wn * 32 + nt * 8 + c0;
            if (col < N_TOT) {
                const float bx = bias[col], by = bias[col + 1];
#pragma unroll
                for (int h = 0; h < 2; h++) {
                    const int row = m0 + wm * 64 + mt * 16 + r0 + h * 8;
                    float2 v;
                    v.x = acc[mt][nt][h * 2 + 0] + bx;
                    v.y = acc[mt][nt][h * 2 + 1] + by;
                    *(float2*)(out + (size_t)row * N_TOT + col) = v;
                }
            }
        }
}

// ---------------------------------------------------------------------------
extern "C" void kernel_launch(void* const* d_in, const int* in_sizes, int n_in,
                              void* d_out, int out_size) {
    const float* x  = (const float*)d_in[0];
    const float* W  = (const float*)d_in[1];
    const float* b  = (const float*)d_in[2];
    const float* lA = (const float*)d_in[3];
    const float* lB = (const float*)d_in[4];
    float* out = (float*)d_out;
    (void)in_sizes; (void)n_in; (void)out_size;

    // one merged prep launch: x->fp16 convert + LoRA-fused W transpose
    prep_kernel<<<CONV_BLOCKS + FUSE_BLOCKS, 256>>>(x, W, lA, lB);

    // fp16 tensor-core GEMM
    cudaFuncSetAttribute(gemm_kernel,
                         cudaFuncAttributeMaxDynamicSharedMemorySize,
                         SMEM_TOTAL);
    dim3 grid(N_PAD / BN, M_TOT / BM);   // (38, 64) = 2432 CTAs
    gemm_kernel<<<grid, 256, SMEM_TOTAL>>>(b, out);
}

// round 13
// speedup vs baseline: 1.0448x; 1.0448x over previous
#include <cuda_runtime.h>
#include <cuda_fp16.h>
#include <cstdint>

// LoRAConv1D: out = x @ W + b + 4.0 * (x @ A) @ B
//   x:[8192,1600]f32  W:[1600,4800]f32  b:[4800]  A:[1600,8]  B:[8,4800]
//
// Single-product fp16 tensor path (sm_103 non-'a' target):
//  1) prep kernel (one launch; fuse blocks scheduled first, conv after):
//     W' = W + 4*A@B -> fp16 transposed [N,K] (N padded 4800->4864),
//     x -> fp16. Streaming (__ldcs) reads keep L2 for g_x/g_w.
//  2) out = fp16(x)*fp16(W') + b, fp32 accum via mma.sync m16n8k16
//     (calibrated rel err 2.9326e-4 < 1e-3)
//  GEMM (R11 form, measured ceiling ~293us: tensor/smem parity at
//  2048 cyc/iter/SM): BM=128 BN=128 BK=64, 256 threads (8 warps, 2x4),
//  warp tile 64x32, 3-stage cp.async (32KB/stage), 2 CTAs/SM,
//  B-fragment software pipelining incl. cross-iteration prefetch.

#define M_TOT 8192
#define N_TOT 4800
#define N_PAD 4864
#define K_TOT 1600
#define RANK  8

#define BM 128
#define BN 128
#define BK 64
#define KITERS (K_TOT / BK)        // 25

// stage layout (bytes): A[128*128] B[128*128]
#define A_OFF 0
#define B_OFF 16384
#define STAGE_BYTES 32768
#define SMEM_TOTAL (3 * STAGE_BYTES)   // 98304 per CTA -> 2 CTAs/SM

// prep kernel split: fuse blocks first (compute-heavy, overlaps conv stream)
#define FUSE_NB (N_TOT / 32)           // 150
#define FUSE_KB (K_TOT / 64)           // 25
#define FUSE_BLOCKS (FUSE_NB * FUSE_KB)  // 3750
#define CONV_BLOCKS 3200               // 3200*256*16 = 13.1M = M*K

// ---------------- device scratch (static, alloc-free) ----------------------
__device__ __half g_x[(size_t)M_TOT * K_TOT];    // fp16 x
__device__ __half g_w[(size_t)N_PAD * K_TOT];    // [N_PAD,K] fp16 W' (pad=0)

// ---------------- helpers ---------------------------------------------------
__device__ __forceinline__ uint32_t smem_u32(const void* p) {
    uint32_t a;
    asm("{ .reg .u64 t; cvta.to.shared.u64 t, %1; cvt.u32.u64 %0, t; }"
        : "=r"(a) : "l"(p));
    return a;
}
// 128B-pitch SW128 swizzle: 16B chunk ch of row -> ch ^ (row & 7).
__device__ __forceinline__ uint32_t swz128(int row, int ch) {
    return (uint32_t)(row * 128 + 16 * (ch ^ (row & 7)));
}
__device__ __forceinline__ void cp16(uint32_t dst, const void* src) {
    asm volatile("cp.async.cg.shared.global [%0], [%1], 16;"
                 :: "r"(dst), "l"(src));
}
#define CP_COMMIT() asm volatile("cp.async.commit_group;")
#define CP_WAIT1()  asm volatile("cp.async.wait_group 1;")

__device__ __forceinline__ void ldm_x4(uint32_t* r, uint32_t addr) {
    asm volatile("ldmatrix.sync.aligned.m8n8.x4.shared.b16 {%0,%1,%2,%3}, [%4];"
                 : "=r"(r[0]), "=r"(r[1]), "=r"(r[2]), "=r"(r[3]) : "r"(addr));
}
__device__ __forceinline__ void mma_f16(float* d, const uint32_t* a,
                                        const uint32_t* b) {
    asm volatile(
        "mma.sync.aligned.m16n8k16.row.col.f32.f16.f16.f32 "
        "{%0,%1,%2,%3}, {%4,%5,%6,%7}, {%8,%9}, {%0,%1,%2,%3};"
        : "+f"(d[0]), "+f"(d[1]), "+f"(d[2]), "+f"(d[3])
        : "r"(a[0]), "r"(a[1]), "r"(a[2]), "r"(a[3]), "r"(b[0]), "r"(b[1]));
}
__device__ __forceinline__ float4 ldcs4(const float* p) {
    float4 v;
    asm volatile("ld.global.cs.v4.f32 {%0,%1,%2,%3}, [%4];"
                 : "=f"(v.x), "=f"(v.y), "=f"(v.z), "=f"(v.w) : "l"(p));
    return v;
}

// ---------------- kernel 1: merged prep (W fuse first, then x convert) ------
__global__ void prep_kernel(const float* __restrict__ x,
                            const float* __restrict__ W,
                            const float* __restrict__ A,
                            const float* __restrict__ Bl) {
    const int tid = threadIdx.x;
    if (blockIdx.x >= FUSE_BLOCKS) {
        // ---- x -> fp16: 16 elems/thread, 2 independent ld/st pairs ----
        const size_t base =
            ((size_t)(blockIdx.x - FUSE_BLOCKS) * 256 + tid) * 16;
        float4 v0 = ldcs4(x + base);
        float4 v1 = ldcs4(x + base + 4);
        float4 v2 = ldcs4(x + base + 8);
        float4 v3 = ldcs4(x + base + 12);
        uint4 p0, p1;
        __half* h0 = (__half*)&p0;
        __half* h1 = (__half*)&p1;
        h0[0] = __float2half_rn(v0.x); h0[1] = __float2half_rn(v0.y);
        h0[2] = __float2half_rn(v0.z); h0[3] = __float2half_rn(v0.w);
        h0[4] = __float2half_rn(v1.x); h0[5] = __float2half_rn(v1.y);
        h0[6] = __float2half_rn(v1.z); h0[7] = __float2half_rn(v1.w);
        h1[0] = __float2half_rn(v2.x); h1[1] = __float2half_rn(v2.y);
        h1[2] = __float2half_rn(v2.z); h1[3] = __float2half_rn(v2.w);
        h1[4] = __float2half_rn(v3.x); h1[5] = __float2half_rn(v3.y);
        h1[6] = __float2half_rn(v3.z); h1[7] = __float2half_rn(v3.w);
        *(uint4*)((char*)g_x + base * 2)      = p0;
        *(uint4*)((char*)g_x + base * 2 + 16) = p1;
        return;
    }

    // ---- fuse part: 32n x 64k tile, coalesced 16B stores ----
    __shared__ uint32_t sh[32][37];
    const int bid = blockIdx.x;
    const int nb = bid % FUSE_NB, kb = bid / FUSE_NB;
    const int n0 = nb * 32, k0 = kb * 64;
    const int tx = tid & 31, ty = tid >> 5;      // 32 x 8

#pragma unroll
    for (int w2 = 0; w2 < 4; w2++) {
        __half pair[2];
#pragma unroll
        for (int e = 0; e < 2; e++) {
            const int k = k0 + ty * 8 + w2 * 2 + e;
            const int n = n0 + tx;
            float acc;
            asm volatile("ld.global.cs.f32 %0, [%1];"
                         : "=f"(acc) : "l"(W + (size_t)k * N_TOT + n));
#pragma unroll
            for (int r = 0; r < RANK; r++)
                acc += 4.0f * A[k * RANK + r] * Bl[r * N_TOT + n];
            pair[e] = __float2half_rn(acc);
        }
        sh[tx][ty * 4 + w2] = *(const uint32_t*)pair;
    }
    __syncthreads();
    {
        const int n_local = tid >> 3;
        const int jw = (tid & 7) * 4;
        uint4 v;
        v.x = sh[n_local][jw + 0];
        v.y = sh[n_local][jw + 1];
        v.z = sh[n_local][jw + 2];
        v.w = sh[n_local][jw + 3];
        *(uint4*)(g_w + (size_t)(n0 + n_local) * K_TOT + k0 + (tid & 7) * 8) = v;
    }
}

// ---------------- kernel 2: fp16 mma.sync GEMM (R11 form) -------------------
// 8 warps: wm = wid&1 (64-row slab), wn = wid>>1 (32-col slab).
// Warp tile 64x32: mt=4 (m16), nt=4 (n8) -> acc[4][4][4] = 64 regs.
__global__ __launch_bounds__(256, 2)
void gemm_kernel(const float* __restrict__ bias, float* __restrict__ out) {
    extern __shared__ char smem[];
    const uint32_t sb = smem_u32(smem);
    const int tid = threadIdx.x, lane = tid & 31, wid = tid >> 5;
    const int wm = wid & 1;
    const int wn = wid >> 1;
    const int m0 = blockIdx.y * BM;
    const int n0 = blockIdx.x * BN;
    const uint32_t l7 = lane & 7;

    uint32_t aBase[4];
#pragma unroll
    for (int mt = 0; mt < 4; mt++)
        aBase[mt] = A_OFF + (uint32_t)(wm * 64 + mt * 16 + (lane & 15)) * 128;
    uint32_t bBase[2];
#pragma unroll
    for (int p = 0; p < 2; p++)
        bBase[p] = B_OFF +
            (uint32_t)(wn * 32 + (2 * p + ((lane >> 4) & 1)) * 8 + l7) * 128;
    const uint32_t aSel = lane >> 4;
    const uint32_t bSel = (lane >> 3) & 1;

    float acc[4][4][4];
#pragma unroll
    for (int i = 0; i < 4; i++)
#pragma unroll
        for (int j = 0; j < 4; j++)
#pragma unroll
            for (int k = 0; k < 4; k++) acc[i][j][k] = 0.0f;

    auto load_stage = [&](int s, int k0) {
        const uint32_t st = sb + s * STAGE_BYTES;
#pragma unroll
        for (int i = 0; i < 4; i++) {
            int idx = tid + i * 256;
            int row = idx >> 3, ch = idx & 7;
            cp16(st + A_OFF + swz128(row, ch),
                 g_x + (size_t)(m0 + row) * K_TOT + k0 + ch * 8);
        }
#pragma unroll
        for (int i = 0; i < 4; i++) {
            int idx = tid + i * 256;
            int row = idx >> 3, ch = idx & 7;
            cp16(st + B_OFF + swz128(row, ch),
                 g_w + (size_t)(n0 + row) * K_TOT + k0 + ch * 8);
        }
    };

    auto xA = [&](int kk) { return 16u * (((uint32_t)(kk * 2) + aSel) ^ l7); };
    auto xB = [&](int kk) { return 16u * (((uint32_t)(kk * 2) + bSel) ^ l7); };

    load_stage(0, 0);       CP_COMMIT();
    load_stage(1, BK);      CP_COMMIT();
    CP_WAIT1();
    __syncthreads();

    uint32_t bf[2][2][4];
    {
        const uint32_t st0 = sb + 0 * STAGE_BYTES;
#pragma unroll
        for (int p = 0; p < 2; p++) ldm_x4(bf[0][p], st0 + bBase[p] + xB(0));
    }

    int cur = 0, nxt = 2;
    for (int t = 0; t < KITERS; t++) {
        const uint32_t st = sb + cur * STAGE_BYTES;

        if (t + 2 < KITERS) load_stage(nxt, (t + 2) * BK);
        CP_COMMIT();

#pragma unroll
        for (int kk = 0; kk < 4; kk++) {
            const int cb = kk & 1, nb2 = cb ^ 1;
            uint32_t a[4][4];
#pragma unroll
            for (int mt = 0; mt < 4; mt++)
                ldm_x4(a[mt], st + aBase[mt] + xA(kk));
            if (kk < 3) {
#pragma unroll
                for (int p = 0; p < 2; p++)
                    ldm_x4(bf[nb2][p], st + bBase[p] + xB(kk + 1));
            }
#pragma unroll
            for (int mt = 0; mt < 4; mt++)
#pragma unroll
                for (int p = 0; p < 2; p++) {
                    mma_f16(acc[mt][2 * p],     a[mt], &bf[cb][p][0]);
                    mma_f16(acc[mt][2 * p + 1], a[mt], &bf[cb][p][2]);
                }
        }

        CP_WAIT1();
        const int nxts = (cur == 2) ? 0 : cur + 1;
        if (t + 1 < KITERS) {
            const uint32_t stn = sb + nxts * STAGE_BYTES;
#pragma unroll
            for (int p = 0; p < 2; p++)
                ldm_x4(bf[0][p], stn + bBase[p] + xB(0));
        }
        __syncthreads();
        cur = nxts;
        nxt = (nxt == 2) ? 0 : nxt + 1;
    }

    const int r0 = lane >> 2, c0 = (lane & 3) * 2;
#pragma unroll
    for (int mt = 0; mt < 4; mt++)
#pragma unroll
        for (int nt = 0; nt < 4; nt++) {
            const int col = n0 + wn * 32 + nt * 8 + c0;
            if (col < N_TOT) {
                const float bx = bias[col], by = bias[col + 1];
#pragma unroll
                for (int h = 0; h < 2; h++) {
                    const int row = m0 + wm * 64 + mt * 16 + r0 + h * 8;
                    float2 v;
                    v.x = acc[mt][nt][h * 2 + 0] + bx;
                    v.y = acc[mt][nt][h * 2 + 1] + by;
                    *(float2*)(out + (size_t)row * N_TOT + col) = v;
                }
            }
        }
}

// ---------------------------------------------------------------------------
extern "C" void kernel_launch(void* const* d_in, const int* in_sizes, int n_in,
                              void* d_out, int out_size) {
    const float* x  = (const float*)d_in[0];
    const float* W  = (const float*)d_in[1];
    const float* b  = (const float*)d_in[2];
    const float* lA = (const float*)d_in[3];
    const float* lB = (const float*)d_in[4];
    float* out = (float*)d_out;
    (void)in_sizes; (void)n_in; (void)out_size;

    // one merged prep launch: LoRA-fused W transpose (first) + x->fp16
    prep_kernel<<<FUSE_BLOCKS + CONV_BLOCKS, 256>>>(x, W, lA, lB);

    // fp16 tensor-core GEMM
    cudaFuncSetAttribute(gemm_kernel,
                         cudaFuncAttributeMaxDynamicSharedMemorySize,
                         SMEM_TOTAL);
    dim3 grid(N_PAD / BN, M_TOT / BM);   // (38, 64) = 2432 CTAs
    gemm_kernel<<<grid, 256, SMEM_TOTAL>>>(b, out);
}

// round 14
// speedup vs baseline: 1.0480x; 1.0031x over previous
#include <cuda_runtime.h>
#include <cuda_fp16.h>
#include <cstdint>

// LoRAConv1D: out = x @ W + b + 4.0 * (x @ A) @ B
//   x:[8192,1600]f32  W:[1600,4800]f32  b:[4800]  A:[1600,8]  B:[8,4800]
//
// Single-product fp16 tensor path (sm_103 non-'a' target):
//  1) prep kernel (one launch; fuse blocks scheduled first, conv after):
//     W' = W + 4*A@B -> fp16 transposed [N,K] (N padded 4800->4864),
//     x -> fp16. Streaming (__ldcs) reads keep L2 for g_x/g_w.
//  2) out = fp16(x)*fp16(W') + b, fp32 accum via mma.sync m16n8k16
//     (calibrated rel err 2.9326e-4 < 1e-3)
//  GEMM (R11 form, measured ceiling ~293us: tensor/smem parity at
//  2048 cyc/iter/SM): BM=128 BN=128 BK=64, 256 threads (8 warps, 2x4),
//  warp tile 64x32, 3-stage cp.async (32KB/stage), 2 CTAs/SM,
//  B-fragment software pipelining incl. cross-iteration prefetch.

#define M_TOT 8192
#define N_TOT 4800
#define N_PAD 4864
#define K_TOT 1600
#define RANK  8

#define BM 128
#define BN 128
#define BK 64
#define KITERS (K_TOT / BK)        // 25

// stage layout (bytes): A[128*128] B[128*128]
#define A_OFF 0
#define B_OFF 16384
#define STAGE_BYTES 32768
#define SMEM_TOTAL (3 * STAGE_BYTES)   // 98304 per CTA -> 2 CTAs/SM

// prep kernel split: fuse blocks first (compute-heavy, overlaps conv stream)
#define FUSE_NB (N_TOT / 32)           // 150
#define FUSE_KB (K_TOT / 64)           // 25
#define FUSE_BLOCKS (FUSE_NB * FUSE_KB)  // 3750
#define CONV_BLOCKS 3200               // 3200*256*16 = 13.1M = M*K

// ---------------- device scratch (static, alloc-free) ----------------------
__device__ __half g_x[(size_t)M_TOT * K_TOT];    // fp16 x
__device__ __half g_w[(size_t)N_PAD * K_TOT];    // [N_PAD,K] fp16 W' (pad=0)

// ---------------- helpers ---------------------------------------------------
__device__ __forceinline__ uint32_t smem_u32(const void* p) {
    uint32_t a;
    asm("{ .reg .u64 t; cvta.to.shared.u64 t, %1; cvt.u32.u64 %0, t; }"
        : "=r"(a) : "l"(p));
    return a;
}
// 128B-pitch SW128 swizzle: 16B chunk ch of row -> ch ^ (row & 7).
__device__ __forceinline__ uint32_t swz128(int row, int ch) {
    return (uint32_t)(row * 128 + 16 * (ch ^ (row & 7)));
}
__device__ __forceinline__ void cp16(uint32_t dst, const void* src) {
    asm volatile("cp.async.cg.shared.global [%0], [%1], 16;"
                 :: "r"(dst), "l"(src));
}
#define CP_COMMIT() asm volatile("cp.async.commit_group;")
#define CP_WAIT1()  asm volatile("cp.async.wait_group 1;")

__device__ __forceinline__ void ldm_x4(uint32_t* r, uint32_t addr) {
    asm volatile("ldmatrix.sync.aligned.m8n8.x4.shared.b16 {%0,%1,%2,%3}, [%4];"
                 : "=r"(r[0]), "=r"(r[1]), "=r"(r[2]), "=r"(r[3]) : "r"(addr));
}
__device__ __forceinline__ void mma_f16(float* d, const uint32_t* a,
                                        const uint32_t* b) {
    asm volatile(
        "mma.sync.aligned.m16n8k16.row.col.f32.f16.f16.f32 "
        "{%0,%1,%2,%3}, {%4,%5,%6,%7}, {%8,%9}, {%0,%1,%2,%3};"
        : "+f"(d[0]), "+f"(d[1]), "+f"(d[2]), "+f"(d[3])
        : "r"(a[0]), "r"(a[1]), "r"(a[2]), "r"(a[3]), "r"(b[0]), "r"(b[1]));
}
__device__ __forceinline__ float4 ldcs4(const float* p) {
    float4 v;
    asm volatile("ld.global.cs.v4.f32 {%0,%1,%2,%3}, [%4];"
                 : "=f"(v.x), "=f"(v.y), "=f"(v.z), "=f"(v.w) : "l"(p));
    return v;
}

// ---------------- kernel 1: merged prep (W fuse first, then x convert) ------
__global__ void prep_kernel(const float* __restrict__ x,
                            const float* __restrict__ W,
                            const float* __restrict__ A,
                            const float* __restrict__ Bl) {
    const int tid = threadIdx.x;
    if (blockIdx.x >= FUSE_BLOCKS) {
        // ---- x -> fp16: 16 elems/thread, 2 independent ld/st pairs ----
        const size_t base =
            ((size_t)(blockIdx.x - FUSE_BLOCKS) * 256 + tid) * 16;
        float4 v0 = ldcs4(x + base);
        float4 v1 = ldcs4(x + base + 4);
        float4 v2 = ldcs4(x + base + 8);
        float4 v3 = ldcs4(x + base + 12);
        uint4 p0, p1;
        __half* h0 = (__half*)&p0;
        __half* h1 = (__half*)&p1;
        h0[0] = __float2half_rn(v0.x); h0[1] = __float2half_rn(v0.y);
        h0[2] = __float2half_rn(v0.z); h0[3] = __float2half_rn(v0.w);
        h0[4] = __float2half_rn(v1.x); h0[5] = __float2half_rn(v1.y);
        h0[6] = __float2half_rn(v1.z); h0[7] = __float2half_rn(v1.w);
        h1[0] = __float2half_rn(v2.x); h1[1] = __float2half_rn(v2.y);
        h1[2] = __float2half_rn(v2.z); h1[3] = __float2half_rn(v2.w);
        h1[4] = __float2half_rn(v3.x); h1[5] = __float2half_rn(v3.y);
        h1[6] = __float2half_rn(v3.z); h1[7] = __float2half_rn(v3.w);
        *(uint4*)((char*)g_x + base * 2)      = p0;
        *(uint4*)((char*)g_x + base * 2 + 16) = p1;
        return;
    }

    // ---- fuse part: 32n x 64k tile, coalesced 16B stores ----
    __shared__ uint32_t sh[32][37];
    const int bid = blockIdx.x;
    const int nb = bid % FUSE_NB, kb = bid / FUSE_NB;
    const int n0 = nb * 32, k0 = kb * 64;
    const int tx = tid & 31, ty = tid >> 5;      // 32 x 8

#pragma unroll
    for (int w2 = 0; w2 < 4; w2++) {
        __half pair[2];
#pragma unroll
        for (int e = 0; e < 2; e++) {
            const int k = k0 + ty * 8 + w2 * 2 + e;
            const int n = n0 + tx;
            float acc;
            asm volatile("ld.global.cs.f32 %0, [%1];"
                         : "=f"(acc) : "l"(W + (size_t)k * N_TOT + n));
#pragma unroll
            for (int r = 0; r < RANK; r++)
                acc += 4.0f * A[k * RANK + r] * Bl[r * N_TOT + n];
            pair[e] = __float2half_rn(acc);
        }
        sh[tx][ty * 4 + w2] = *(const uint32_t*)pair;
    }
    __syncthreads();
    {
        const int n_local = tid >> 3;
        const int jw = (tid & 7) * 4;
        uint4 v;
        v.x = sh[n_local][jw + 0];
        v.y = sh[n_local][jw + 1];
        v.z = sh[n_local][jw + 2];
        v.w = sh[n_local][jw + 3];
        *(uint4*)(g_w + (size_t)(n0 + n_local) * K_TOT + k0 + (tid & 7) * 8) = v;
    }
}

// ---------------- kernel 2: fp16 mma.sync GEMM (R11 form) -------------------
// 8 warps: wm = wid&1 (64-row slab), wn = wid>>1 (32-col slab).
// Warp tile 64x32: mt=4 (m16), nt=4 (n8) -> acc[4][4][4] = 64 regs.
__global__ __launch_bounds__(256, 2)
void gemm_kernel(const float* __restrict__ bias, float* __restrict__ out) {
    extern __shared__ char smem[];
    const uint32_t sb = smem_u32(smem);
    const int tid = threadIdx.x, lane = tid & 31, wid = tid >> 5;
    const int wm = wid & 1;
    const int wn = wid >> 1;
    const int m0 = blockIdx.y * BM;
    const int n0 = blockIdx.x * BN;
    const uint32_t l7 = lane & 7;

    uint32_t aBase[4];
#pragma unroll
    for (int mt = 0; mt < 4; mt++)
        aBase[mt] = A_OFF + (uint32_t)(wm * 64 + mt * 16 + (lane & 15)) * 128;
    uint32_t bBase[2];
#pragma unroll
    for (int p = 0; p < 2; p++)
        bBase[p] = B_OFF +
            (uint32_t)(wn * 32 + (2 * p + ((lane >> 4) & 1)) * 8 + l7) * 128;
    const uint32_t aSel = lane >> 4;
    const uint32_t bSel = (lane >> 3) & 1;

    float acc[4][4][4];
#pragma unroll
    for (int i = 0; i < 4; i++)
#pragma unroll
        for (int j = 0; j < 4; j++)
#pragma unroll
            for (int k = 0; k < 4; k++) acc[i][j][k] = 0.0f;

    auto load_stage = [&](int s, int k0) {
        const uint32_t st = sb + s * STAGE_BYTES;
#pragma unroll
        for (int i = 0; i < 4; i++) {
            int idx = tid + i * 256;
            int row = idx >> 3, ch = idx & 7;
            cp16(st + A_OFF + swz128(row, ch),
                 g_x + (size_t)(m0 + row) * K_TOT + k0 + ch * 8);
        }
#pragma unroll
        for (int i = 0; i < 4; i++) {
            int idx = tid + i * 256;
            int row = idx >> 3, ch = idx & 7;
            cp16(st + B_OFF + swz128(row, ch),
                 g_w + (size_t)(n0 + row) * K_TOT + k0 + ch * 8);
        }
    };

    auto xA = [&](int kk) { return 16u * (((uint32_t)(kk * 2) + aSel) ^ l7); };
    auto xB = [&](int kk) { return 16u * (((uint32_t)(kk * 2) + bSel) ^ l7); };

    load_stage(0, 0);       CP_COMMIT();
    load_stage(1, BK);      CP_COMMIT();
    CP_WAIT1();
    __syncthreads();

    uint32_t bf[2][2][4];
    {
        const uint32_t st0 = sb + 0 * STAGE_BYTES;
#pragma unroll
        for (int p = 0; p < 2; p++) ldm_x4(bf[0][p], st0 + bBase[p] + xB(0));
    }

    int cur = 0, nxt = 2;
    for (int t = 0; t < KITERS; t++) {
        const uint32_t st = sb + cur * STAGE_BYTES;

        if (t + 2 < KITERS) load_stage(nxt, (t + 2) * BK);
        CP_COMMIT();

#pragma unroll
        for (int kk = 0; kk < 4; kk++) {
            const int cb = kk & 1, nb2 = cb ^ 1;
            uint32_t a[4][4];
#pragma unroll
            for (int mt = 0; mt < 4; mt++)
                ldm_x4(a[mt], st + aBase[mt] + xA(kk));
            if (kk < 3) {
#pragma unroll
                for (int p = 0; p < 2; p++)
                    ldm_x4(bf[nb2][p], st + bBase[p] + xB(kk + 1));
            }
#pragma unroll
            for (int mt = 0; mt < 4; mt++)
#pragma unroll
                for (int p = 0; p < 2; p++) {
                    mma_f16(acc[mt][2 * p],     a[mt], &bf[cb][p][0]);
                    mma_f16(acc[mt][2 * p + 1], a[mt], &bf[cb][p][2]);
                }
        }

        CP_WAIT1();
        const int nxts = (cur == 2) ? 0 : cur + 1;
        if (t + 1 < KITERS) {
            const uint32_t stn = sb + nxts * STAGE_BYTES;
#pragma unroll
            for (int p = 0; p < 2; p++)
                ldm_x4(bf[0][p], stn + bBase[p] + xB(0));
        }
        __syncthreads();
        cur = nxts;
        nxt = (nxt == 2) ? 0 : nxt + 1;
    }

    const int r0 = lane >> 2, c0 = (lane & 3) * 2;
#pragma unroll
    for (int mt = 0; mt < 4; mt++)
#pragma unroll
        for (int nt = 0; nt < 4; nt++) {
            const int col = n0 + wn * 32 + nt * 8 + c0;
            if (col < N_TOT) {
                const float bx = bias[col], by = bias[col + 1];
#pragma unroll
                for (int h = 0; h < 2; h++) {
                    const int row = m0 + wm * 64 + mt * 16 + r0 + h * 8;
                    float2 v;
                    v.x = acc[mt][nt][h * 2 + 0] + bx;
                    v.y = acc[mt][nt][h * 2 + 1] + by;
                    *(float2*)(out + (size_t)row * N_TOT + col) = v;
                }
            }
        }
}

// ---------------------------------------------------------------------------
extern "C" void kernel_launch(void* const* d_in, const int* in_sizes, int n_in,
                              void* d_out, int out_size) {
    const float* x  = (const float*)d_in[0];
    const float* W  = (const float*)d_in[1];
    const float* b  = (const float*)d_in[2];
    const float* lA = (const float*)d_in[3];
    const float* lB = (const float*)d_in[4];
    float* out = (float*)d_out;
    (void)in_sizes; (void)n_in; (void)out_size;

    // one merged prep launch: LoRA-fused W transpose (first) + x->fp16
    prep_kernel<<<FUSE_BLOCKS + CONV_BLOCKS, 256>>>(x, W, lA, lB);

    // fp16 tensor-core GEMM
    cudaFuncSetAttribute(gemm_kernel,
                         cudaFuncAttributeMaxDynamicSharedMemorySize,
                         SMEM_TOTAL);
    dim3 grid(N_PAD / BN, M_TOT / BM);   // (38, 64) = 2432 CTAs
    gemm_kernel<<<grid, 256, SMEM_TOTAL>>>(b, out);
}